// round 1
// baseline (speedup 1.0000x reference)
#include <cuda_runtime.h>
#include <cstdint>
#include <math.h>

#define T_SEQ   256
#define BATCH   16
#define NINP    400
#define NHID    1150
#define VOCABP1 33279
#define M_TOK   (BATCH * T_SEQ)   // 4096

// ---------------- scratch (static device globals; no allocation) ----------------
__device__ float g_xa[(size_t)M_TOK * NHID];          // ping  (max width 1150)
__device__ float g_xb[(size_t)M_TOK * NHID];          // pong
__device__ float g_xg[(size_t)M_TOK * 4 * NHID];      // gate preactivations (max 4096x4600)
__device__ float g_h[2][BATCH * NHID];                // recurrent h ping-pong, layout [u][b]
__device__ float g_c[BATCH * NHID];                   // cell state, layout [u][b]
__device__ unsigned g_bar;                            // grid barrier counter

// ---------------- grid barrier (monotonic counter; reset kernel between launches) ----
__device__ __forceinline__ void grid_sync(unsigned target) {
    __syncthreads();
    if (threadIdx.x == 0) {
        __threadfence();
        atomicAdd(&g_bar, 1u);
        while (*(volatile unsigned*)&g_bar < target) { __nanosleep(40); }
        __threadfence();
    }
    __syncthreads();
}

__global__ void bar_reset_k() { g_bar = 0u; }

// ---------------- embedding gather ----------------
__global__ void embed_k(const int* __restrict__ tok, const float* __restrict__ emb,
                        float* __restrict__ x0) {
    int m = blockIdx.x;                  // m = b*T + t
    int t = tok[m];
    const float4* src = (const float4*)(emb + (size_t)t * NINP);
    float4* dst = (float4*)(x0 + (size_t)m * NINP);
    for (int i = threadIdx.x; i < NINP / 4; i += blockDim.x) dst[i] = src[i];
}

// ---------------- SGEMM: C[M,N] = A[M,K] * B (+bias) ----------------
// BTRANS=false: B is [K,N] row-major.  BTRANS=true: B is [N,K] row-major (C = A*B^T).
// M must be a multiple of 128 (always 4096 here). N,K arbitrary.
template<bool BTRANS, bool BIAS>
__global__ __launch_bounds__(256) void sgemm_k(
    const float* __restrict__ A, const float* __restrict__ B,
    const float* __restrict__ bias, float* __restrict__ C,
    int M, int N, int K)
{
    __shared__ float As[8][128];
    __shared__ float Bs[8][132];

    const int tid = threadIdx.x;
    const int bm = blockIdx.y * 128;
    const int bn = blockIdx.x * 128;
    const int tr = (tid >> 4) * 8;      // 0..120
    const int tc = (tid & 15) * 8;      // 0..120

    float acc[8][8];
#pragma unroll
    for (int y = 0; y < 8; y++)
#pragma unroll
        for (int x = 0; x < 8; x++) acc[y][x] = 0.f;

    const int a_m = tid >> 1;           // 0..127
    const int a_k = (tid & 1) * 4;      // 0 or 4

    for (int k0 = 0; k0 < K; k0 += 8) {
        // load A tile (transposed into As[k][m])
#pragma unroll
        for (int i = 0; i < 4; i++) {
            int gk = k0 + a_k + i;
            As[a_k + i][a_m] = (gk < K) ? A[(size_t)(bm + a_m) * K + gk] : 0.f;
        }
        // load B tile into Bs[k][n]
        if (BTRANS) {
            int n = tid >> 1;
            int kk = (tid & 1) * 4;
            int gn = bn + n;
            float v[4] = {0.f, 0.f, 0.f, 0.f};
            if (gn < N) {
                int gk = k0 + kk;
                if (((K & 3) == 0) && (gk + 3 < K)) {
                    float4 t4 = *(const float4*)&B[(size_t)gn * K + gk];
                    v[0] = t4.x; v[1] = t4.y; v[2] = t4.z; v[3] = t4.w;
                } else {
#pragma unroll
                    for (int i = 0; i < 4; i++)
                        if (gk + i < K) v[i] = B[(size_t)gn * K + gk + i];
                }
            }
#pragma unroll
            for (int i = 0; i < 4; i++) Bs[kk + i][n] = v[i];
        } else {
            int bk = tid >> 5;
            int nn = (tid & 31) * 4;
            int gk = k0 + bk;
            int gn = bn + nn;
            if (gk < K && gn + 3 < N) {
                float4 v = *(const float4*)&B[(size_t)gk * N + gn];
                *(float4*)&Bs[bk][nn] = v;
            } else {
#pragma unroll
                for (int i = 0; i < 4; i++)
                    Bs[bk][nn + i] = (gk < K && gn + i < N) ? B[(size_t)gk * N + gn + i] : 0.f;
            }
        }
        __syncthreads();

#pragma unroll
        for (int kk = 0; kk < 8; kk++) {
            float aF[8], bF[8];
            *(float4*)&aF[0] = *(const float4*)&As[kk][tr];
            *(float4*)&aF[4] = *(const float4*)&As[kk][tr + 4];
            *(float4*)&bF[0] = *(const float4*)&Bs[kk][tc];
            *(float4*)&bF[4] = *(const float4*)&Bs[kk][tc + 4];
#pragma unroll
            for (int y = 0; y < 8; y++)
#pragma unroll
                for (int x = 0; x < 8; x++) acc[y][x] = fmaf(aF[y], bF[x], acc[y][x]);
        }
        __syncthreads();
    }

#pragma unroll
    for (int y = 0; y < 8; y++) {
        int gm = bm + tr + y;
#pragma unroll
        for (int x = 0; x < 8; x++) {
            int gn = bn + tc + x;
            if (gn < N) {
                float v = acc[y][x];
                if (BIAS) v += bias[gn];
                C[(size_t)gm * N + gn] = v;
            }
        }
    }
}

// ---------------- persistent LSTM recurrence (one layer) ----------------
// grid = NCTA, block = 256. Each CTA owns 8 units (x4 gates = 32 dot columns).
// 256 threads = 32 column-lanes x 8 k-chunks. One grid barrier per timestep.
template<int U, int NCTA>
__global__ __launch_bounds__(256) void lstm_k(
    const float* __restrict__ Um,   // [U][4U]
    const float* __restrict__ xg,   // [4096][4U], row m = b*T + t
    float* __restrict__ xout)       // [4096][U]
{
    constexpr int N4 = 4 * U;
    constexpr int KC = (U + 7) / 8;

    extern __shared__ float sm[];
    float* h_s = sm;                      // [U][16]  (k-major, batch inner)
    float* red = sm + U * 16;             // [16][256] : red[b*256 + tid]
    float* gat = red + 16 * 256;          // [32][16]

    const int tid  = threadIdx.x;
    const int lane = tid & 31;
    const int kc   = tid >> 5;
    const int g    = lane >> 3;           // gate 0..3 (i,f,c,o)
    const int ul   = lane & 7;
    const int u    = blockIdx.x * 8 + ul;
    const bool uok = (u < U);
    const int j    = g * U + u;
    const int k0   = kc * KC;
    const int k1   = (k0 + KC < U) ? (k0 + KC) : U;

    // zero state
    for (int idx = blockIdx.x * 256 + tid; idx < 16 * U; idx += NCTA * 256) {
        g_h[0][idx] = 0.f; g_h[1][idx] = 0.f; g_c[idx] = 0.f;
    }
    unsigned gen = 1;
    grid_sync(gen * NCTA);

    for (int t = 0; t < T_SEQ; ++t) {
        const float* hg = g_h[t & 1];
        float* hn = g_h[(t & 1) ^ 1];

        // stage h into shared (L2 read: cross-CTA data, bypass L1)
        for (int idx = tid; idx < U * 16; idx += 256) h_s[idx] = __ldcg(&hg[idx]);
        __syncthreads();

        float acc[16];
#pragma unroll
        for (int b = 0; b < 16; b++) acc[b] = 0.f;

        if (uok) {
            const float* Up = Um + j;
#pragma unroll 4
            for (int k = k0; k < k1; ++k) {
                float uv = __ldg(&Up[(size_t)k * N4]);
                const float4* hv = (const float4*)(h_s + (k << 4));
                float4 ha = hv[0], hb = hv[1], hc = hv[2], hd = hv[3];
                acc[0]  = fmaf(ha.x, uv, acc[0]);
                acc[1]  = fmaf(ha.y, uv, acc[1]);
                acc[2]  = fmaf(ha.z, uv, acc[2]);
                acc[3]  = fmaf(ha.w, uv, acc[3]);
                acc[4]  = fmaf(hb.x, uv, acc[4]);
                acc[5]  = fmaf(hb.y, uv, acc[5]);
                acc[6]  = fmaf(hb.z, uv, acc[6]);
                acc[7]  = fmaf(hb.w, uv, acc[7]);
                acc[8]  = fmaf(hc.x, uv, acc[8]);
                acc[9]  = fmaf(hc.y, uv, acc[9]);
                acc[10] = fmaf(hc.z, uv, acc[10]);
                acc[11] = fmaf(hc.w, uv, acc[11]);
                acc[12] = fmaf(hd.x, uv, acc[12]);
                acc[13] = fmaf(hd.y, uv, acc[13]);
                acc[14] = fmaf(hd.z, uv, acc[14]);
                acc[15] = fmaf(hd.w, uv, acc[15]);
            }
        }
#pragma unroll
        for (int b = 0; b < 16; b++) red[b * 256 + tid] = acc[b];
        __syncthreads();

        // reduce across the 8 k-chunks: 512 outputs (32 cols x 16 batches)
#pragma unroll
        for (int o = tid; o < 512; o += 256) {
            int c = o & 31, b = o >> 5;
            float s = 0.f;
#pragma unroll
            for (int q = 0; q < 8; q++) s += red[b * 256 + q * 32 + c];
            int gg = c >> 3;
            int uu = blockIdx.x * 8 + (c & 7);
            if (uu < U) {
                s += __ldg(&xg[((size_t)b * T_SEQ + t) * N4 + (size_t)gg * U + uu]);
                gat[c * 16 + b] = s;
            }
        }
        __syncthreads();

        // gate math + state update (128 (b,u) pairs per CTA)
        if (tid < 128) {
            int b = tid & 15, w = tid >> 4;
            int uu = blockIdx.x * 8 + w;
            if (uu < U) {
                float iv = gat[(0 * 8 + w) * 16 + b];
                float fv = gat[(1 * 8 + w) * 16 + b];
                float cg = gat[(2 * 8 + w) * 16 + b];
                float ov = gat[(3 * 8 + w) * 16 + b];
                iv = 1.f / (1.f + __expf(-iv));
                fv = 1.f / (1.f + __expf(-fv));
                ov = 1.f / (1.f + __expf(-ov));
                cg = tanhf(cg);
                float cold = g_c[uu * 16 + b];
                float cn = fv * cold + iv * cg;
                float hv = ov * tanhf(cn);
                g_c[uu * 16 + b] = cn;
                hn[uu * 16 + b] = hv;
                xout[((size_t)b * T_SEQ + t) * U + uu] = hv;
            }
        }
        gen++;
        grid_sync(gen * NCTA);
    }
}

// ---------------- in-place row softmax over N columns ----------------
__global__ __launch_bounds__(256) void softmax_k(float* __restrict__ out, int N) {
    int m = blockIdx.x;
    float* row = out + (size_t)m * N;
    __shared__ float s1[8];
    __shared__ float sb;
    int tid = threadIdx.x, wid = tid >> 5, ln = tid & 31;

    float lm = -3.4e38f;
    for (int i = tid; i < N; i += 256) lm = fmaxf(lm, row[i]);
#pragma unroll
    for (int o = 16; o; o >>= 1) lm = fmaxf(lm, __shfl_xor_sync(0xffffffffu, lm, o));
    if (!ln) s1[wid] = lm;
    __syncthreads();
    if (tid == 0) {
        float v = s1[0];
#pragma unroll
        for (int q = 1; q < 8; q++) v = fmaxf(v, s1[q]);
        sb = v;
    }
    __syncthreads();
    float mx = sb;
    __syncthreads();

    float ls = 0.f;
    for (int i = tid; i < N; i += 256) ls += __expf(row[i] - mx);
#pragma unroll
    for (int o = 16; o; o >>= 1) ls += __shfl_xor_sync(0xffffffffu, ls, o);
    if (!ln) s1[wid] = ls;
    __syncthreads();
    if (tid == 0) {
        float v = 0.f;
#pragma unroll
        for (int q = 0; q < 8; q++) v += s1[q];
        sb = 1.f / v;
    }
    __syncthreads();
    float inv = sb;

    for (int i = tid; i < N; i += 256) row[i] = __expf(row[i] - mx) * inv;
}

// ---------------- launch ----------------
extern "C" void kernel_launch(void* const* d_in, const int* in_sizes, int n_in,
                              void* d_out, int out_size)
{
    (void)in_sizes; (void)n_in; (void)out_size;
    const int*   tok = (const int*)d_in[0];
    const float* emb = (const float*)d_in[1];
    const float* W0  = (const float*)d_in[2];
    const float* U0  = (const float*)d_in[3];
    const float* b0  = (const float*)d_in[4];
    const float* W1  = (const float*)d_in[5];
    const float* U1  = (const float*)d_in[6];
    const float* b1  = (const float*)d_in[7];
    const float* W2  = (const float*)d_in[8];
    const float* U2  = (const float*)d_in[9];
    const float* b2  = (const float*)d_in[10];
    float* out = (float*)d_out;

    float *xa, *xb, *xg;
    cudaGetSymbolAddress((void**)&xa, g_xa);
    cudaGetSymbolAddress((void**)&xb, g_xb);
    cudaGetSymbolAddress((void**)&xg, g_xg);

    const int SMEM_BIG   = (NHID * 16 + 256 * 16 + 32 * 16) * 4;   // 92032
    const int SMEM_SMALL = (NINP * 16 + 256 * 16 + 32 * 16) * 4;   // 44032
    cudaFuncSetAttribute(lstm_k<NHID, 144>, cudaFuncAttributeMaxDynamicSharedMemorySize, SMEM_BIG);
    cudaFuncSetAttribute(lstm_k<NINP, 50>,  cudaFuncAttributeMaxDynamicSharedMemorySize, SMEM_SMALL);

    // 1) embedding
    embed_k<<<M_TOK, 128>>>(tok, emb, xa);

    // 2) layer 0: xg = x @ W0 + b0 ; recurrence
    sgemm_k<false, true><<<dim3((4 * NHID + 127) / 128, M_TOK / 128), 256>>>(
        xa, W0, b0, xg, M_TOK, 4 * NHID, NINP);
    bar_reset_k<<<1, 1>>>();
    lstm_k<NHID, 144><<<144, 256, SMEM_BIG>>>(U0, xg, xb);

    // 3) layer 1
    sgemm_k<false, true><<<dim3((4 * NHID + 127) / 128, M_TOK / 128), 256>>>(
        xb, W1, b1, xg, M_TOK, 4 * NHID, NHID);
    bar_reset_k<<<1, 1>>>();
    lstm_k<NHID, 144><<<144, 256, SMEM_BIG>>>(U1, xg, xa);

    // 4) layer 2 (units = 400)
    sgemm_k<false, true><<<dim3((4 * NINP + 127) / 128, M_TOK / 128), 256>>>(
        xa, W2, b2, xg, M_TOK, 4 * NINP, NHID);
    bar_reset_k<<<1, 1>>>();
    lstm_k<NINP, 50><<<50, 256, SMEM_SMALL>>>(U2, xg, xb);

    // 5) tied decode: logits = x @ emb^T   -> write straight into d_out
    sgemm_k<true, false><<<dim3((VOCABP1 + 127) / 128, M_TOK / 128), 256>>>(
        xb, emb, nullptr, out, M_TOK, VOCABP1, NINP);

    // 6) in-place softmax
    softmax_k<<<M_TOK, 256>>>(out, VOCABP1);
}